// round 5
// baseline (speedup 1.0000x reference)
#include <cuda_runtime.h>

// Problem constants (fixed: points shape (4, 8192, 3) fp32)
#define BATCH    4
#define NPTS     8192
#define NQ_TOT   (BATCH * NPTS)     // 32768
#define NN_SIZE  16
#define NK       17                  // 16 neighbors + self slot
#define RADIUS2  0.25f
#define EPS      1e-4f

#define SPLITS   8
#define CHUNK    (NPTS / SPLITS)     // 1024 candidates per block
#define BLOCK    128
#define QPT      2                   // queries per thread
#define QPB      (BLOCK * QPT)       // 256 queries per block
#define CAP      96                  // per-thread per-chunk within-radius buffer

// Partial sorted top-NK arrays: [chunk][slot][query] for coalesced access.
__device__ float g_scratch[SPLITS * NK * NQ_TOT];   // 17.8 MB static scratch

__global__ void zero_out_kernel(float* out) {
    if (threadIdx.x == 0) out[0] = 0.0f;
}

// Pass 1: each block = (256 queries, 2 per thread) x (one 1024-candidate chunk).
// Emits the chunk-local capped top-17 d^2 per query.
__global__ void __launch_bounds__(BLOCK)
knn_chunk_kernel(const float* __restrict__ pts) {
    __shared__ __align__(16) float4 tile[CHUNK];    // (x, y, z, |c|^2) : 16 KB

    const int q0    = blockIdx.x * QPB + threadIdx.x;         // [0, NQ_TOT)
    const int q1    = q0 + BLOCK;
    const int chunk = blockIdx.y;
    const int b     = q0 / NPTS;                               // 256-aligned => same batch for q0,q1
    const float* __restrict__ bpts = pts + (size_t)b * NPTS * 3;

    // Load chunk into smem with precomputed squared norm
    for (int i = threadIdx.x; i < CHUNK; i += BLOCK) {
        const float* p = bpts + (chunk * CHUNK + i) * 3;
        const float x = p[0], y = p[1], z = p[2];
        tile[i] = make_float4(x, y, z, fmaf(x, x, fmaf(y, y, z * z)));
    }

    // Query registers (two queries per thread)
    const float ax = pts[q0 * 3 + 0], ay = pts[q0 * 3 + 1], az = pts[q0 * 3 + 2];
    const float bx = pts[q1 * 3 + 0], by = pts[q1 * 3 + 1], bz = pts[q1 * 3 + 2];
    const float as  = fmaf(ax, ax, fmaf(ay, ay, az * az));
    const float bs  = fmaf(bx, bx, fmaf(by, by, bz * bz));
    const float a2x = -2.0f * ax, a2y = -2.0f * ay, a2z = -2.0f * az;
    const float b2x = -2.0f * bx, b2y = -2.0f * by, b2z = -2.0f * bz;

    __syncthreads();

    // Hot loop: one LDS.128 feeds both queries' distance evals.
    // d^2 = |q|^2 + |c|^2 - 2 q.c
    float buf0[CAP], buf1[CAP];     // local memory, rare predicated appends
    int   n0 = 0, n1 = 0;
#pragma unroll 8
    for (int j = 0; j < CHUNK; ++j) {
        const float4 c = tile[j];
        float t0 = as + c.w;
        t0 = fmaf(a2x, c.x, t0);
        t0 = fmaf(a2y, c.y, t0);
        t0 = fmaf(a2z, c.z, t0);
        float t1 = bs + c.w;
        t1 = fmaf(b2x, c.x, t1);
        t1 = fmaf(b2y, c.y, t1);
        t1 = fmaf(b2z, c.z, t1);
        if (t0 < RADIUS2) { if (n0 < CAP) buf0[n0] = t0; ++n0; }
        if (t1 < RADIUS2) { if (n1 < CAP) buf1[n1] = t1; ++n1; }
    }
    if (n0 > CAP) n0 = CAP;
    if (n1 > CAP) n1 = CAP;

    // Build sorted ascending top-NK (capped at RADIUS2) from each buffer.
    float a[NK], d[NK];
#pragma unroll
    for (int k = 0; k < NK; ++k) { a[k] = RADIUS2; d[k] = RADIUS2; }
    for (int i = 0; i < n0; ++i) {
        const float v = buf0[i];
#pragma unroll
        for (int k = NK - 1; k > 0; --k)
            a[k] = (v < a[k]) ? fmaxf(v, a[k - 1]) : a[k];
        a[0] = fminf(a[0], v);
    }
    for (int i = 0; i < n1; ++i) {
        const float v = buf1[i];
#pragma unroll
        for (int k = NK - 1; k > 0; --k)
            d[k] = (v < d[k]) ? fmaxf(v, d[k - 1]) : d[k];
        d[0] = fminf(d[0], v);
    }

    // Coalesced scatter: slot-major layout
#pragma unroll
    for (int k = 0; k < NK; ++k) {
        g_scratch[(chunk * NK + k) * NQ_TOT + q0] = a[k];
        g_scratch[(chunk * NK + k) * NQ_TOT + q1] = d[k];
    }
}

// Pass 2: merge the SPLITS sorted partials per query, apply f, reduce.
__global__ void __launch_bounds__(BLOCK)
merge_kernel(float* __restrict__ out) {
    const int qidx = blockIdx.x * BLOCK + threadIdx.x;

    float m[NK];
#pragma unroll
    for (int k = 0; k < NK; ++k) m[k] = RADIUS2;

    for (int c = 0; c < SPLITS; ++c) {
        const float* __restrict__ base = g_scratch + (size_t)(c * NK) * NQ_TOT + qidx;
#pragma unroll
        for (int k = 0; k < NK; ++k) {
            const float v = base[k * NQ_TOT];
            if (v >= m[NK - 1]) break;   // chunk array sorted ascending
#pragma unroll
            for (int t = NK - 1; t > 0; --t)
                m[t] = (v < m[t]) ? fmaxf(v, m[t - 1]) : m[t];
            m[0] = fminf(m[0], v);
        }
    }

    // m[0] is the query itself (d^2 ~ 0, global minimum). Sum f over m[1..16].
    float s = 0.0f;
#pragma unroll
    for (int k = 1; k < NK; ++k) {
        const float v = m[k];
        if (v < RADIUS2) s += rsqrtf(v + EPS);
    }
    s *= (1.0f / (float)(NQ_TOT * NN_SIZE));   // fold in the mean

    // Warp + block reduction -> atomicAdd
#pragma unroll
    for (int off = 16; off > 0; off >>= 1)
        s += __shfl_xor_sync(0xFFFFFFFFu, s, off);

    __shared__ float wsum[BLOCK / 32];
    const int lane = threadIdx.x & 31;
    const int wid  = threadIdx.x >> 5;
    if (lane == 0) wsum[wid] = s;
    __syncthreads();
    if (threadIdx.x == 0) {
        float t = 0.0f;
#pragma unroll
        for (int w = 0; w < BLOCK / 32; ++w) t += wsum[w];
        atomicAdd(out, t);
    }
}

extern "C" void kernel_launch(void* const* d_in, const int* in_sizes, int n_in,
                              void* d_out, int out_size) {
    const float* pts = (const float*)d_in[0];
    float* out = (float*)d_out;

    zero_out_kernel<<<1, 32>>>(out);

    dim3 grid1(NQ_TOT / QPB, SPLITS);
    knn_chunk_kernel<<<grid1, BLOCK>>>(pts);

    merge_kernel<<<NQ_TOT / BLOCK, BLOCK>>>(out);
}